// round 6
// baseline (speedup 1.0000x reference)
#include <cuda_runtime.h>
#include <cstdint>
#include <cstddef>

#define C_DIM 256
#define H_DIM 96
#define W_DIM 96
#define TW 24
#define TH 8
#define NPAIR 3
#define RAD 4
#define CC 8
#define NSTAGE (C_DIM / CC)                  // 32
#define S1_STRIDE 40
#define S2_STRIDE 40
#define S2_ROWS (TH + 8)                     // 16
#define S1_WORDS (CC * TH * S1_STRIDE)       // 2560
#define S2_WORDS (CC * S2_ROWS * S2_STRIDE)  // 5120
#define STAGE_WORDS (S1_WORDS + S2_WORDS)    // 7680
#define STAGE_BYTES (STAGE_WORDS * 4)
#define NBUF 3
#define NTHREADS 288
#define N_IN1_CHUNKS (CC * TH * (TW / 4))            // 384
#define N_IN2_CHUNKS (CC * S2_ROWS * ((TW + 8) / 4)) // 1024
#define N_CHUNKS (N_IN1_CHUNKS + N_IN2_CHUNKS)       // 1408
#define NFULL 4                                      // full chunk rounds
#define CADV (CC * H_DIM * W_DIM)                    // channel advance per stage (floats)

typedef unsigned long long u64;

union F2U { float2 f2; u64 u; };

__device__ __forceinline__ void fma2(u64 &d, u64 a, u64 b) {
    asm("fma.rn.f32x2 %0, %1, %2, %0;" : "+l"(d) : "l"(a), "l"(b));
}
__device__ __forceinline__ void cp16(uint32_t s, const float* g, uint32_t vbit) {
    int sz = vbit ? 16 : 0;
    asm volatile("cp.async.cg.shared.global [%0], [%1], 16, %2;\n"
                 :: "r"(s), "l"(g), "r"(sz));
}

__global__ __launch_bounds__(NTHREADS, 2)
void corr_kernel(const float* __restrict__ in1, const float* __restrict__ in2,
                 float* __restrict__ out) {
    extern __shared__ float smem[];
    const int tid = threadIdx.x;
    const int w0 = blockIdx.x * TW;
    const int h0 = blockIdx.y * TH;
    const int b  = blockIdx.z;

    const int ph   = tid >> 5;          // warp id = displacement row 0..8
    const int lane = tid & 31;
    const int pc   = lane & 3;          // 6-px block 0..3
    const int r    = lane >> 2;         // tile row 0..7
    const int x0   = pc * 6;

    // ---- hoisted load addressing (computed once) ----
    const float* gptr[NFULL + 1];
    uint32_t     meta[NFULL + 1];       // smem byte offset | (valid << 31)
    const bool   tail = (tid < N_CHUNKS - NFULL * NTHREADS);  // tid < 256 (warps 0..7)
#pragma unroll
    for (int j = 0; j <= NFULL; j++) {
        int i = tid + j * NTHREADS;
        if (j == NFULL && !tail) { gptr[j] = in1; meta[j] = 0; continue; }
        if (i < N_IN1_CHUNKS) {
            int c   = i / (TH * (TW / 4));
            int rem = i % (TH * (TW / 4));
            int row = rem / (TW / 4);
            int ch  = rem % (TW / 4);
            gptr[j] = in1 + (((size_t)(b * C_DIM + c) * H_DIM + (h0 + row)) * W_DIM + w0 + ch * 4);
            meta[j] = (uint32_t)(((c * TH + row) * S1_STRIDE + ch * 4) * 4) | 0x80000000u;
        } else {
            int ii  = i - N_IN1_CHUNKS;
            int c   = ii / (S2_ROWS * 8);
            int rem = ii % (S2_ROWS * 8);
            int row = rem / 8;
            int ch  = rem % 8;
            int h2 = h0 + row - RAD;
            int w2 = w0 + ch * 4 - RAD;
            bool valid = (h2 >= 0) && (h2 < H_DIM) && (w2 >= 0) && (w2 <= W_DIM - 4);
            gptr[j] = in2 + (((size_t)(b * C_DIM + c) * H_DIM + (valid ? h2 : 0)) * W_DIM +
                             (valid ? w2 : 0));
            meta[j] = (uint32_t)(S1_WORDS * 4 +
                      ((c * S2_ROWS + row) * S2_STRIDE + ch * 4) * 4) |
                      (valid ? 0x80000000u : 0u);
        }
    }

    u64 accE[NPAIR][5];
    float accO[NPAIR][4][2];
#pragma unroll
    for (int k = 0; k < NPAIR; k++) {
#pragma unroll
        for (int d = 0; d < 5; d++) accE[k][d] = 0ull;
#pragma unroll
        for (int d = 0; d < 4; d++) { accO[k][d][0] = 0.f; accO[k][d][1] = 0.f; }
    }

    const uint32_t sb0 = (uint32_t)__cvta_generic_to_shared(smem);

    auto load_stage = [&](int buf) {
        const uint32_t sbase = sb0 + (uint32_t)(buf * STAGE_BYTES);
#pragma unroll
        for (int j = 0; j < NFULL; j++) {
            cp16(sbase + (meta[j] & 0x7FFFFFFFu), gptr[j], meta[j] & 0x80000000u);
            gptr[j] += CADV;
        }
        if (tail) {
            cp16(sbase + (meta[NFULL] & 0x7FFFFFFFu), gptr[NFULL], meta[NFULL] & 0x80000000u);
            gptr[NFULL] += CADV;
        }
        asm volatile("cp.async.commit_group;\n");
    };

    load_stage(0);
    load_stage(1);

    int bufc = 0;
    int bufl = 2;
    for (int s = 0; s < NSTAGE; s++) {
        if (s < NSTAGE - 1) {
            asm volatile("cp.async.wait_group 1;\n");
        } else {
            asm volatile("cp.async.wait_group 0;\n");
        }
        __syncthreads();
        if (s + 2 < NSTAGE) load_stage(bufl);

        const float* s1p = smem + bufc * STAGE_WORDS;
        const float* s2p = s1p + S1_WORDS;
#pragma unroll
        for (int cc = 0; cc < CC; cc++) {
            const float2* v1row = (const float2*)(s1p + (cc * TH + r) * S1_STRIDE + x0);
            F2U v1[NPAIR];
#pragma unroll
            for (int q = 0; q < NPAIR; q++) v1[q].f2 = v1row[q];

            const float2* v2row = (const float2*)(s2p + (cc * S2_ROWS + (r + ph)) * S2_STRIDE + x0);
            F2U v2[7];
#pragma unroll
            for (int q = 0; q < 7; q++) v2[q].f2 = v2row[q];

#pragma unroll
            for (int k = 0; k < NPAIR; k++)
#pragma unroll
                for (int dh = 0; dh < 5; dh++)
                    fma2(accE[k][dh], v1[k].u, v2[k + dh].u);

#pragma unroll
            for (int k = 0; k < NPAIR; k++)
#pragma unroll
                for (int dh = 0; dh < 4; dh++) {
                    accO[k][dh][0] = __fmaf_rn(v1[k].f2.x, v2[k + dh].f2.y, accO[k][dh][0]);
                    accO[k][dh][1] = __fmaf_rn(v1[k].f2.y, v2[k + dh + 1].f2.x, accO[k][dh][1]);
                }
        }

        bufc = (bufc == NBUF - 1) ? 0 : bufc + 1;
        bufl = (bufl == NBUF - 1) ? 0 : bufl + 1;
    }

    // epilogue
    const size_t plane = (size_t)H_DIM * W_DIM;
    float* op = out + (size_t)(b * 81 + ph * 9) * plane +
                (size_t)(h0 + r) * W_DIM + (w0 + x0);
#pragma unroll
    for (int dh = 0; dh < 5; dh++) {
        u64* orow = (u64*)(op + (size_t)(2 * dh) * plane);
#pragma unroll
        for (int k = 0; k < NPAIR; k++) orow[k] = accE[k][dh];
    }
#pragma unroll
    for (int dh = 0; dh < 4; dh++) {
        float* orow = op + (size_t)(2 * dh + 1) * plane;
#pragma unroll
        for (int k = 0; k < NPAIR; k++) {
            F2U t; t.f2.x = accO[k][dh][0]; t.f2.y = accO[k][dh][1];
            *(u64*)(orow + 2 * k) = t.u;
        }
    }
}

extern "C" void kernel_launch(void* const* d_in, const int* in_sizes, int n_in,
                              void* d_out, int out_size) {
    const float* in1 = (const float*)d_in[0];
    const float* in2 = (const float*)d_in[1];
    float* out = (float*)d_out;
    int Bn = in_sizes[0] / (C_DIM * H_DIM * W_DIM);
    size_t smem_bytes = (size_t)NBUF * STAGE_BYTES;  // 92160
    cudaFuncSetAttribute(corr_kernel, cudaFuncAttributeMaxDynamicSharedMemorySize,
                         (int)smem_bytes);
    dim3 grid(W_DIM / TW, H_DIM / TH, Bn);
    corr_kernel<<<grid, NTHREADS, smem_bytes>>>(in1, in2, out);
}